// round 12
// baseline (speedup 1.0000x reference)
#include <cuda_runtime.h>
#include <cuda_fp16.h>

#define NCFG 21

__constant__ int c_kh[NCFG] = {74,60,49,93,76,62, 148,120,98,186,152,124,
                               235,192,156,296,241,197,373,304,248};
__constant__ int c_kw[NCFG] = {49,60,74,62,76,93, 98,120,148,124,152,186,
                               156,192,235,197,241,296,248,304,373};
__constant__ int c_off[NCFG] = {0,3626,7226,10852,16618,22394,
                                28160,42664,57064,71568,94632,117736,
                                140800,177460,214324,250984,309296,367377,
                                425689,518193,610609};
// total area = 703113 pixels; scratch: [cfg][bk(32)][pixel], half4 packed in float2
#define TOTAL_AGG 22499616
__device__ float2 g_aggh[TOTAL_AGG];   // 180 MB

// x in column-pitched layout: [row 0..3583][PITCH], data at cols [XOFF, XOFF+448),
// zero guard strips at [0,XOFF) and [XOFF+448, PITCH).
#define PITCH 768
#define XOFF  128
#define XROWS 3584
__device__ float4 g_xp[XROWS * PITCH];   // 44 MB

// Tap tables
__device__ float4 g_tyw[NCFG][224];
__device__ int4   g_tyo[NCFG][224];   // row offsets premultiplied by kw
__device__ float4 g_txw[NCFG][224];
__device__ int4   g_txo[NCFG][224];   // column offsets (float2 units)

// ---------------- packed f32x2 helpers ----------------
__device__ __forceinline__ unsigned long long f2pack(float lo, float hi) {
    unsigned long long r;
    asm("mov.b64 %0, {%1, %2};" : "=l"(r) : "f"(lo), "f"(hi));
    return r;
}
__device__ __forceinline__ void funpack(unsigned long long v, float& lo, float& hi) {
    asm("mov.b64 {%0, %1}, %2;" : "=f"(lo), "=f"(hi) : "l"(v));
}
__device__ __forceinline__ void ffma2(unsigned long long& d,
                                      unsigned long long a, unsigned long long b) {
    asm("fma.rn.f32x2 %0, %1, %2, %0;" : "+l"(d) : "l"(a), "l"(b));
}

__device__ __forceinline__ float2 pack_h4(float a, float b, float c) {
    union { float2 f; __half2 h[2]; } u;
    u.h[0] = __floats2half2_rn(a, b);
    u.h[1] = __floats2half2_rn(c, 0.0f);
    return u.f;
}

// ---------------------------------------------------------------------------
// Prep: blocks [0,3584) fill one pitched row each (data + zero strips);
// blocks [3584,3626) compute taps. Block = 448 threads.
// ---------------------------------------------------------------------------
__global__ void __launch_bounds__(448) prep_kernel(const float* __restrict__ x) {
    if (blockIdx.x < XROWS) {
        const int rb = blockIdx.x;
        const int t  = threadIdx.x;
        float4* drow = g_xp + (size_t)rb * PITCH;
        const float4 z = make_float4(0.f, 0.f, 0.f, 0.f);
        if (t < 128)      drow[t] = z;                       // left strip
        else if (t < 320) drow[XOFF + 448 + (t - 128)] = z;  // right strip (192)
        const float* src = x + ((size_t)rb * 448 + t) * 3;
        drow[XOFF + t] = make_float4(src[0], src[1], src[2], 0.0f);
        return;
    }
    const int bi  = blockIdx.x - XROWS;     // 0..41
    const int cfg = bi % NCFG;
    const int dim = bi / NCFG;              // 0 = rows(kh), 1 = cols(kw)
    const int o   = threadIdx.x;
    if (o >= 224) return;

    const int n  = dim ? c_kw[cfg] : c_kh[cfg];
    const int kw = c_kw[cfg];

    const double ks = (n > 224) ? (double)n / 224.0 : 1.0;
    const double sf = ((double)o + 0.5) * (double)n / 224.0 - 0.5;
    const int NT = (n < 224) ? 2 : (2 * n) / 224 + 1;   // 2..4
    int lo = (int)ceil(sf - ks);

    double w[4];
    double tot = 0.0;
    for (int t = 0; t < 4; ++t) {
        double v = 0.0;
        if (t < NT) {
            int j = lo + t;
            if (j >= 0 && j < n) {
                v = 1.0 - fabs(sf - (double)j) / ks;
                if (v < 0.0) v = 0.0;
            }
        }
        w[t] = v;
        tot += v;
    }
    const double r = 1.0 / tot;

    float wf[4];
    int   of[4];
    for (int t = 0; t < 4; ++t) {
        wf[t] = (float)(w[t] * r);
        int j = lo + t;
        if (j < 0) j = 0;
        if (j > n - 1) j = n - 1;
        of[t] = dim ? j : j * kw;
    }
    if (dim == 0) {
        g_tyw[cfg][o] = make_float4(wf[0], wf[1], wf[2], wf[3]);
        g_tyo[cfg][o] = make_int4(of[0], of[1], of[2], of[3]);
    } else {
        g_txw[cfg][o] = make_float4(wf[0], wf[1], wf[2], wf[3]);
        g_txo[cfg][o] = make_int4(of[0], of[1], of[2], of[3]);
    }
}

// ---------------------------------------------------------------------------
// Row-based agg for p3/p4 (agg5 recipe): block = (row i, batch b) of one cfg,
// threads = columns. g bounds block-uniform; h loop fully in-range via guard
// strips (unconditional loads); k-pair packed FFMA2, 1 LDS.128 per tap.
// grid = (kh, 8), blockDim >= kw (per-cfg launch).
// ---------------------------------------------------------------------------
template<int S, int G, int A>
__global__ void agg_row_kernel(const float* __restrict__ wsrc, int cfg, int a) {
    const int kh = c_kh[cfg], kw = c_kw[cfg];
    const int i = blockIdx.x;
    const int b = blockIdx.y;
    constexpr int G2 = G * G;

    __shared__ ulonglong2 swp2[G2];   // swp2[gh] = {(k0,k1),(k2,k3)}
    {
        const float* wb = wsrc + (size_t)(b * A + a) * 4 * G2;
        for (int t = threadIdx.x; t < 2 * G2; t += blockDim.x) {
            const int gh = t >> 1, kp = t & 1;
            const float v0 = wb[(2 * kp)     * G2 + gh];
            const float v1 = wb[(2 * kp + 1) * G2 + gh];
            ((unsigned long long*)swp2)[2 * gh + kp] = f2pack(v0, v1);
        }
    }
    __syncthreads();

    const int j = threadIdx.x;
    if (j >= kw) return;

    const int p0 = (kh - S + 1) >> 1;
    const int p1 = (kw - S + 1) >> 1;
    const int ri = i - p0;
    const int cj = j - p1;

    unsigned long long acc[3][2] = {{0ull,0ull},{0ull,0ull},{0ull,0ull}};

    const float4* base = g_xp + ((long long)(b * 448) + ri) * PITCH + XOFF + cj;

    for (int g = 0; g < G; ++g) {
        const int r = g * S + ri;
        if ((unsigned)r <= 447u) {            // block-uniform
            const float4* rowp = base + g * (S * PITCH);
            const ulonglong2* wg = swp2 + g * G;
#pragma unroll 4
            for (int h = 0; h < G; ++h) {
                const float4 xv = __ldg(rowp + h * S);
                const unsigned long long xx = f2pack(xv.x, xv.x);
                const unsigned long long xy = f2pack(xv.y, xv.y);
                const unsigned long long xz = f2pack(xv.z, xv.z);
                const ulonglong2 w2 = wg[h];
                ffma2(acc[0][0], w2.x, xx);
                ffma2(acc[1][0], w2.x, xy);
                ffma2(acc[2][0], w2.x, xz);
                ffma2(acc[0][1], w2.y, xx);
                ffma2(acc[1][1], w2.y, xy);
                ffma2(acc[2][1], w2.y, xz);
            }
        }
    }

    const int area = kh * kw;
    float2* dst = g_aggh + (size_t)32 * c_off[cfg] + (size_t)(b * 4) * area
                + (size_t)i * kw + j;
#pragma unroll
    for (int kp = 0; kp < 2; ++kp) {
        float c0a, c0b, c1a, c1b, c2a, c2b;
        funpack(acc[0][kp], c0a, c0b);
        funpack(acc[1][kp], c1a, c1b);
        funpack(acc[2][kp], c2a, c2b);
        __stcs(dst + (size_t)(2 * kp)     * area, pack_h4(c0a, c1a, c2a));
        __stcs(dst + (size_t)(2 * kp + 1) * area, pack_h4(c0b, c1b, c2b));
    }
}

// ---------------------------------------------------------------------------
// Specialized p5 agg (unchanged from R11).
// ---------------------------------------------------------------------------
__global__ void __launch_bounds__(256) agg5_kernel(const float* __restrict__ w5) {
    const int cfg = 12 + blockIdx.z;
    const int kh = c_kh[cfg], kw = c_kw[cfg];
    const int by = blockIdx.y;
    const int b  = by / 373;
    const int i  = by - b * 373;
    if (i >= kh) return;
    const int j0 = blockIdx.x * 256;
    if (j0 >= kw) return;

    __shared__ ulonglong2 swp2[16];
    {
        const int t = threadIdx.x;
        if (t < 32) {
            const int gh = t >> 1, kp = t & 1;
            const size_t wb = (size_t)(b * 9 + blockIdx.z) * 4;
            const float v0 = w5[(wb + 2 * kp)     * 16 + gh];
            const float v1 = w5[(wb + 2 * kp + 1) * 16 + gh];
            ((unsigned long long*)swp2)[2 * gh + kp] = f2pack(v0, v1);
        }
    }
    __syncthreads();

    const int j = j0 + threadIdx.x;
    if (j >= kw) return;

    const int p0 = (kh - 127) >> 1;
    const int p1 = (kw - 127) >> 1;
    const int ri = i - p0;
    const int cj = j - p1;

    unsigned long long acc[3][2] = {{0ull,0ull},{0ull,0ull},{0ull,0ull}};

    const float4* base = g_xp + ((long long)(b * 448) + ri) * PITCH + XOFF + cj;

#pragma unroll
    for (int g = 0; g < 4; ++g) {
        const int r = g * 128 + ri;
        if ((unsigned)r <= 447u) {
            float4 xv[4];
#pragma unroll
            for (int h = 0; h < 4; ++h)
                xv[h] = __ldg(base + g * (128 * PITCH) + h * 128);
#pragma unroll
            for (int h = 0; h < 4; ++h) {
                const unsigned long long xx = f2pack(xv[h].x, xv[h].x);
                const unsigned long long xy = f2pack(xv[h].y, xv[h].y);
                const unsigned long long xz = f2pack(xv[h].z, xv[h].z);
                const ulonglong2 w2 = swp2[g * 4 + h];
                ffma2(acc[0][0], w2.x, xx);
                ffma2(acc[1][0], w2.x, xy);
                ffma2(acc[2][0], w2.x, xz);
                ffma2(acc[0][1], w2.y, xx);
                ffma2(acc[1][1], w2.y, xy);
                ffma2(acc[2][1], w2.y, xz);
            }
        }
    }

    const int area = kh * kw;
    float2* dst = g_aggh + (size_t)32 * c_off[cfg] + (size_t)(b * 4) * area
                + (size_t)i * kw + j;
#pragma unroll
    for (int kp = 0; kp < 2; ++kp) {
        float c0a, c0b, c1a, c1b, c2a, c2b;
        funpack(acc[0][kp], c0a, c0b);
        funpack(acc[1][kp], c1a, c1b);
        funpack(acc[2][kp], c2a, c2b);
        __stcs(dst + (size_t)(2 * kp)     * area, pack_h4(c0a, c1a, c2a));
        __stcs(dst + (size_t)(2 * kp + 1) * area, pack_h4(c0b, c1b, c2b));
    }
}

// ---------------------------------------------------------------------------
// Kernel B (R8 version): fully unrolled per-cfg separable resize accumulation.
// ---------------------------------------------------------------------------
template<int AREA, int OFF, int NR, int NC>
__device__ __forceinline__ void do_cfg(int cfg, int bk, int ox,
                                       const float (*s_yw)[4], const int (*s_yo)[4],
                                       float& a0, float& a1, float& a2) {
    const float2* base = g_aggh + (size_t)32 * OFF + (size_t)bk * AREA;
    const float4 xw = g_txw[cfg][ox];
    const int4   xo = g_txo[cfg][ox];
    const float xwv[4] = {xw.x, xw.y, xw.z, xw.w};
    const int   xov[4] = {xo.x, xo.y, xo.z, xo.w};
#pragma unroll
    for (int r = 0; r < NR; ++r) {
        const float wy = s_yw[cfg][r];
        const float2* p = base + s_yo[cfg][r];
#pragma unroll
        for (int c = 0; c < NC; ++c) {
            const float w = wy * xwv[c];
            union { float2 f; __half2 h[2]; } u;
            u.f = __ldg(p + xov[c]);
            const float2 lo = __half22float2(u.h[0]);
            const float  hi = __low2float(u.h[1]);
            a0 += w * lo.x;
            a1 += w * lo.y;
            a2 += w * hi;
        }
    }
}

__global__ void __launch_bounds__(224) resize_kernel(float* __restrict__ out) {
    const int oy = blockIdx.x;
    const int bk = blockIdx.y;
    const int ox = threadIdx.x;

    __shared__ float s_yw[NCFG][4];
    __shared__ int   s_yo[NCFG][4];
    {
        const int t = threadIdx.x;
        if (t < NCFG * 4) {
            const int cfg = t >> 2, k = t & 3;
            s_yw[cfg][k] = ((const float*)&g_tyw[cfg][oy])[k];
            s_yo[cfg][k] = ((const int*)&g_tyo[cfg][oy])[k];
        }
    }
    __syncthreads();

    float a0 = 0.0f, a1 = 0.0f, a2 = 0.0f;

    do_cfg< 3626,      0, 2, 2>( 0, bk, ox, s_yw, s_yo, a0, a1, a2);
    do_cfg< 3600,   3626, 2, 2>( 1, bk, ox, s_yw, s_yo, a0, a1, a2);
    do_cfg< 3626,   7226, 2, 2>( 2, bk, ox, s_yw, s_yo, a0, a1, a2);
    do_cfg< 5766,  10852, 2, 2>( 3, bk, ox, s_yw, s_yo, a0, a1, a2);
    do_cfg< 5776,  16618, 2, 2>( 4, bk, ox, s_yw, s_yo, a0, a1, a2);
    do_cfg< 5766,  22394, 2, 2>( 5, bk, ox, s_yw, s_yo, a0, a1, a2);
    do_cfg<14504,  28160, 2, 2>( 6, bk, ox, s_yw, s_yo, a0, a1, a2);
    do_cfg<14400,  42664, 2, 2>( 7, bk, ox, s_yw, s_yo, a0, a1, a2);
    do_cfg<14504,  57064, 2, 2>( 8, bk, ox, s_yw, s_yo, a0, a1, a2);
    do_cfg<23064,  71568, 2, 2>( 9, bk, ox, s_yw, s_yo, a0, a1, a2);
    do_cfg<23104,  94632, 2, 2>(10, bk, ox, s_yw, s_yo, a0, a1, a2);
    do_cfg<23064, 117736, 2, 2>(11, bk, ox, s_yw, s_yo, a0, a1, a2);
    do_cfg<36660, 140800, 3, 2>(12, bk, ox, s_yw, s_yo, a0, a1, a2);
    do_cfg<36864, 177460, 2, 2>(13, bk, ox, s_yw, s_yo, a0, a1, a2);
    do_cfg<36660, 214324, 2, 3>(14, bk, ox, s_yw, s_yo, a0, a1, a2);
    do_cfg<58312, 250984, 3, 2>(15, bk, ox, s_yw, s_yo, a0, a1, a2);
    do_cfg<58081, 309296, 3, 3>(16, bk, ox, s_yw, s_yo, a0, a1, a2);
    do_cfg<58312, 367377, 2, 3>(17, bk, ox, s_yw, s_yo, a0, a1, a2);
    do_cfg<92504, 425689, 4, 3>(18, bk, ox, s_yw, s_yo, a0, a1, a2);
    do_cfg<92416, 518193, 3, 3>(19, bk, ox, s_yw, s_yo, a0, a1, a2);
    do_cfg<92504, 610609, 3, 4>(20, bk, ox, s_yw, s_yo, a0, a1, a2);

    float* o = out + ((size_t)(bk * 224 + oy) * 224 + ox) * 3;
    o[0] = a0;
    o[1] = a1;
    o[2] = a2;
}

// ---------------------------------------------------------------------------
extern "C" void kernel_launch(void* const* d_in, const int* in_sizes, int n_in,
                              void* d_out, int out_size) {
    const float* x  = (const float*)d_in[0];
    const float* w3 = (const float*)d_in[1];
    const float* w4 = (const float*)d_in[2];
    const float* w5 = (const float*)d_in[3];

    prep_kernel<<<XROWS + 42, 448>>>(x);

    // p3: per-cfg row kernels, blockDim = kw rounded up to 32
    static const int h3_kh[6] = {74,60,49,93,76,62};
    static const int h3_bd[6] = {64,64,96,64,96,96};
    for (int c = 0; c < 6; ++c)
        agg_row_kernel<32, 14, 6><<<dim3(h3_kh[c], 8), h3_bd[c]>>>(w3, c, c);

    // p4
    static const int h4_kh[6] = {148,120,98,186,152,124};
    static const int h4_bd[6] = {128,128,160,128,160,192};
    for (int c = 0; c < 6; ++c)
        agg_row_kernel<64, 7, 6><<<dim3(h4_kh[c], 8), h4_bd[c]>>>(w4, 6 + c, c);

    agg5_kernel<<<dim3(2, 8 * 373, 9), 256>>>(w5);

    dim3 gridB(224, 32);
    resize_kernel<<<gridB, 224>>>((float*)d_out);
}

// round 13
// speedup vs baseline: 1.7169x; 1.7169x over previous
#include <cuda_runtime.h>
#include <cuda_fp16.h>

#define NCFG 21

__constant__ int c_kh[NCFG] = {74,60,49,93,76,62, 148,120,98,186,152,124,
                               235,192,156,296,241,197,373,304,248};
__constant__ int c_kw[NCFG] = {49,60,74,62,76,93, 98,120,148,124,152,186,
                               156,192,235,197,241,296,248,304,373};
__constant__ int c_off[NCFG] = {0,3626,7226,10852,16618,22394,
                                28160,42664,57064,71568,94632,117736,
                                140800,177460,214324,250984,309296,367377,
                                425689,518193,610609};
// total area = 703113 pixels; scratch: [cfg][bk(32)][pixel], half4 packed in float2
#define TOTAL_AGG 22499616
__device__ float2 g_aggh[TOTAL_AGG];   // 180 MB

// x pitched with column AND per-batch row guards:
//   index(b, r, c) = ((b*RPB) + ROWOFF + r)*PITCH + XOFF + c
//   valid r in [0,448), guards r in [-64,0) and [448,512) are zero rows;
//   valid c in [0,448), zero strips at [-128,0) and [448,640).
#define PITCH  768
#define XOFF   128
#define ROWOFF 64
#define RPB    576
#define TOTROWS (8 * RPB)      // 4608
__device__ float4 g_xp[TOTROWS * PITCH];   // 56.6 MB

// Tap tables
__device__ float4 g_tyw[NCFG][224];
__device__ int4   g_tyo[NCFG][224];   // row offsets premultiplied by kw
__device__ float4 g_txw[NCFG][224];
__device__ int4   g_txo[NCFG][224];   // column offsets (float2 units)

// ---------------- packed f32x2 helpers ----------------
__device__ __forceinline__ unsigned long long f2pack(float lo, float hi) {
    unsigned long long r;
    asm("mov.b64 %0, {%1, %2};" : "=l"(r) : "f"(lo), "f"(hi));
    return r;
}
__device__ __forceinline__ void funpack(unsigned long long v, float& lo, float& hi) {
    asm("mov.b64 {%0, %1}, %2;" : "=f"(lo), "=f"(hi) : "l"(v));
}
__device__ __forceinline__ void ffma2(unsigned long long& d,
                                      unsigned long long a, unsigned long long b) {
    asm("fma.rn.f32x2 %0, %1, %2, %0;" : "+l"(d) : "l"(a), "l"(b));
}

__device__ __forceinline__ float2 pack_h4(float a, float b, float c) {
    union { float2 f; __half2 h[2]; } u;
    u.h[0] = __floats2half2_rn(a, b);
    u.h[1] = __floats2half2_rn(c, 0.0f);
    return u.f;
}

// ---------------------------------------------------------------------------
// Prep: blocks [0,4608) fill one pitched row each (data or zero guard row);
// blocks [4608,4650) compute taps. Block = 448 threads.
// ---------------------------------------------------------------------------
__global__ void __launch_bounds__(448) prep_kernel(const float* __restrict__ x) {
    if (blockIdx.x < TOTROWS) {
        const int rb = blockIdx.x;
        const int b    = rb / RPB;
        const int rloc = rb - b * RPB;
        const int r    = rloc - ROWOFF;
        const int t  = threadIdx.x;
        float4* drow = g_xp + (size_t)rb * PITCH;
        const float4 z = make_float4(0.f, 0.f, 0.f, 0.f);
        if ((unsigned)r < 448u) {
            if (t < 128)      drow[t] = z;                       // left strip
            else if (t < 320) drow[XOFF + 448 + (t - 128)] = z;  // right strip
            const float* src = x + ((size_t)(b * 448 + r) * 448 + t) * 3;
            drow[XOFF + t] = make_float4(src[0], src[1], src[2], 0.0f);
        } else {
            drow[t] = z;
            if (t < 320) drow[448 + t] = z;
        }
        return;
    }
    const int bi  = blockIdx.x - TOTROWS;   // 0..41
    const int cfg = bi % NCFG;
    const int dim = bi / NCFG;              // 0 = rows(kh), 1 = cols(kw)
    const int o   = threadIdx.x;
    if (o >= 224) return;

    const int n  = dim ? c_kw[cfg] : c_kh[cfg];
    const int kw = c_kw[cfg];

    const double ks = (n > 224) ? (double)n / 224.0 : 1.0;
    const double sf = ((double)o + 0.5) * (double)n / 224.0 - 0.5;
    const int NT = (n < 224) ? 2 : (2 * n) / 224 + 1;   // 2..4
    int lo = (int)ceil(sf - ks);

    double w[4];
    double tot = 0.0;
    for (int t = 0; t < 4; ++t) {
        double v = 0.0;
        if (t < NT) {
            int j = lo + t;
            if (j >= 0 && j < n) {
                v = 1.0 - fabs(sf - (double)j) / ks;
                if (v < 0.0) v = 0.0;
            }
        }
        w[t] = v;
        tot += v;
    }
    const double r = 1.0 / tot;

    float wf[4];
    int   of[4];
    for (int t = 0; t < 4; ++t) {
        wf[t] = (float)(w[t] * r);
        int j = lo + t;
        if (j < 0) j = 0;
        if (j > n - 1) j = n - 1;
        of[t] = dim ? j : j * kw;
    }
    if (dim == 0) {
        g_tyw[cfg][o] = make_float4(wf[0], wf[1], wf[2], wf[3]);
        g_tyo[cfg][o] = make_int4(of[0], of[1], of[2], of[3]);
    } else {
        g_txw[cfg][o] = make_float4(wf[0], wf[1], wf[2], wf[3]);
        g_txo[cfg][o] = make_int4(of[0], of[1], of[2], of[3]);
    }
}

// ---------------------------------------------------------------------------
// p3/p4 agg: flat pixel index per cfg (chip-filling grid), ZERO bounds checks
// (row+col guards give true zeros). Per tap: 1 LDG.128 + 3 packs + 6 FFMA2.
// ---------------------------------------------------------------------------
template<int S, int G, int A, int CFG0>
__global__ void __launch_bounds__(256) agg34_kernel(const float* __restrict__ wsrc) {
    const int cfg = CFG0 + blockIdx.z;
    const int kh = c_kh[cfg], kw = c_kw[cfg];
    const int area = kh * kw;
    if ((int)(blockIdx.x * 256) >= area) return;

    const int a = blockIdx.z;
    const int b = blockIdx.y;
    constexpr int G2 = G * G;

    __shared__ ulonglong2 swp2[G2];   // swp2[gh] = {(k0,k1),(k2,k3)}
    {
        const float* wb = wsrc + (size_t)(b * A + a) * 4 * G2;
        for (int t = threadIdx.x; t < 2 * G2; t += 256) {
            const int gh = t >> 1, kp = t & 1;
            const float v0 = wb[(2 * kp)     * G2 + gh];
            const float v1 = wb[(2 * kp + 1) * G2 + gh];
            ((unsigned long long*)swp2)[2 * gh + kp] = f2pack(v0, v1);
        }
    }
    __syncthreads();

    const int idx = blockIdx.x * 256 + threadIdx.x;
    if (idx >= area) return;

    const int i = idx / kw;
    const int j = idx - i * kw;
    const int p0 = (kh - S + 1) >> 1;
    const int p1 = (kw - S + 1) >> 1;
    const int ri = i - p0;
    const int cj = j - p1;

    unsigned long long acc[3][2] = {{0ull,0ull},{0ull,0ull},{0ull,0ull}};

    const float4* base = g_xp + ((size_t)(b * RPB) + ROWOFF + ri) * PITCH + XOFF + cj;

#pragma unroll 2
    for (int g = 0; g < G; ++g) {
        const float4* rowp = base + g * (S * PITCH);
        const ulonglong2* wg = swp2 + g * G;
#pragma unroll 7
        for (int h = 0; h < G; ++h) {
            const float4 xv = __ldg(rowp + h * S);
            const unsigned long long xx = f2pack(xv.x, xv.x);
            const unsigned long long xy = f2pack(xv.y, xv.y);
            const unsigned long long xz = f2pack(xv.z, xv.z);
            const ulonglong2 w2 = wg[h];
            ffma2(acc[0][0], w2.x, xx);
            ffma2(acc[1][0], w2.x, xy);
            ffma2(acc[2][0], w2.x, xz);
            ffma2(acc[0][1], w2.y, xx);
            ffma2(acc[1][1], w2.y, xy);
            ffma2(acc[2][1], w2.y, xz);
        }
    }

    float2* dst = g_aggh + (size_t)32 * c_off[cfg] + (size_t)(b * 4) * area + idx;
#pragma unroll
    for (int kp = 0; kp < 2; ++kp) {
        float c0a, c0b, c1a, c1b, c2a, c2b;
        funpack(acc[0][kp], c0a, c0b);
        funpack(acc[1][kp], c1a, c1b);
        funpack(acc[2][kp], c2a, c2b);
        __stcs(dst + (size_t)(2 * kp)     * area, pack_h4(c0a, c1a, c2a));
        __stcs(dst + (size_t)(2 * kp + 1) * area, pack_h4(c0b, c1b, c2b));
    }
}

// ---------------------------------------------------------------------------
// Specialized p5 agg (R11 form, rebased onto new x layout).
// ---------------------------------------------------------------------------
__global__ void __launch_bounds__(256) agg5_kernel(const float* __restrict__ w5) {
    const int cfg = 12 + blockIdx.z;
    const int kh = c_kh[cfg], kw = c_kw[cfg];
    const int by = blockIdx.y;
    const int b  = by / 373;
    const int i  = by - b * 373;
    if (i >= kh) return;
    const int j0 = blockIdx.x * 256;
    if (j0 >= kw) return;

    __shared__ ulonglong2 swp2[16];
    {
        const int t = threadIdx.x;
        if (t < 32) {
            const int gh = t >> 1, kp = t & 1;
            const size_t wb = (size_t)(b * 9 + blockIdx.z) * 4;
            const float v0 = w5[(wb + 2 * kp)     * 16 + gh];
            const float v1 = w5[(wb + 2 * kp + 1) * 16 + gh];
            ((unsigned long long*)swp2)[2 * gh + kp] = f2pack(v0, v1);
        }
    }
    __syncthreads();

    const int j = j0 + threadIdx.x;
    if (j >= kw) return;

    const int p0 = (kh - 127) >> 1;
    const int p1 = (kw - 127) >> 1;
    const int ri = i - p0;
    const int cj = j - p1;

    unsigned long long acc[3][2] = {{0ull,0ull},{0ull,0ull},{0ull,0ull}};

    const float4* base = g_xp + ((size_t)(b * RPB) + ROWOFF + ri) * PITCH + XOFF + cj;

#pragma unroll
    for (int g = 0; g < 4; ++g) {
        const int r = g * 128 + ri;
        if ((unsigned)r <= 447u) {            // uniform across block
            float4 xv[4];
#pragma unroll
            for (int h = 0; h < 4; ++h)
                xv[h] = __ldg(base + g * (128 * PITCH) + h * 128);
#pragma unroll
            for (int h = 0; h < 4; ++h) {
                const unsigned long long xx = f2pack(xv[h].x, xv[h].x);
                const unsigned long long xy = f2pack(xv[h].y, xv[h].y);
                const unsigned long long xz = f2pack(xv[h].z, xv[h].z);
                const ulonglong2 w2 = swp2[g * 4 + h];
                ffma2(acc[0][0], w2.x, xx);
                ffma2(acc[1][0], w2.x, xy);
                ffma2(acc[2][0], w2.x, xz);
                ffma2(acc[0][1], w2.y, xx);
                ffma2(acc[1][1], w2.y, xy);
                ffma2(acc[2][1], w2.y, xz);
            }
        }
    }

    const int area = kh * kw;
    float2* dst = g_aggh + (size_t)32 * c_off[cfg] + (size_t)(b * 4) * area
                + (size_t)i * kw + j;
#pragma unroll
    for (int kp = 0; kp < 2; ++kp) {
        float c0a, c0b, c1a, c1b, c2a, c2b;
        funpack(acc[0][kp], c0a, c0b);
        funpack(acc[1][kp], c1a, c1b);
        funpack(acc[2][kp], c2a, c2b);
        __stcs(dst + (size_t)(2 * kp)     * area, pack_h4(c0a, c1a, c2a));
        __stcs(dst + (size_t)(2 * kp + 1) * area, pack_h4(c0b, c1b, c2b));
    }
}

// ---------------------------------------------------------------------------
// Kernel B: fully unrolled per-cfg separable resize accumulation (half4 loads).
// ---------------------------------------------------------------------------
template<int AREA, int OFF, int NR, int NC>
__device__ __forceinline__ void do_cfg(int cfg, int bk, int ox,
                                       const float (*s_yw)[4], const int (*s_yo)[4],
                                       float& a0, float& a1, float& a2) {
    const float2* base = g_aggh + (size_t)32 * OFF + (size_t)bk * AREA;
    const float4 xw = g_txw[cfg][ox];
    const int4   xo = g_txo[cfg][ox];
    const float xwv[4] = {xw.x, xw.y, xw.z, xw.w};
    const int   xov[4] = {xo.x, xo.y, xo.z, xo.w};
#pragma unroll
    for (int r = 0; r < NR; ++r) {
        const float wy = s_yw[cfg][r];
        const float2* p = base + s_yo[cfg][r];
#pragma unroll
        for (int c = 0; c < NC; ++c) {
            const float w = wy * xwv[c];
            union { float2 f; __half2 h[2]; } u;
            u.f = __ldg(p + xov[c]);
            const float2 lo = __half22float2(u.h[0]);
            const float  hi = __low2float(u.h[1]);
            a0 += w * lo.x;
            a1 += w * lo.y;
            a2 += w * hi;
        }
    }
}

__global__ void __launch_bounds__(224) resize_kernel(float* __restrict__ out) {
    const int oy = blockIdx.x;
    const int bk = blockIdx.y;
    const int ox = threadIdx.x;

    __shared__ float s_yw[NCFG][4];
    __shared__ int   s_yo[NCFG][4];
    {
        const int t = threadIdx.x;
        if (t < NCFG * 4) {
            const int cfg = t >> 2, k = t & 3;
            s_yw[cfg][k] = ((const float*)&g_tyw[cfg][oy])[k];
            s_yo[cfg][k] = ((const int*)&g_tyo[cfg][oy])[k];
        }
    }
    __syncthreads();

    float a0 = 0.0f, a1 = 0.0f, a2 = 0.0f;

    do_cfg< 3626,      0, 2, 2>( 0, bk, ox, s_yw, s_yo, a0, a1, a2);
    do_cfg< 3600,   3626, 2, 2>( 1, bk, ox, s_yw, s_yo, a0, a1, a2);
    do_cfg< 3626,   7226, 2, 2>( 2, bk, ox, s_yw, s_yo, a0, a1, a2);
    do_cfg< 5766,  10852, 2, 2>( 3, bk, ox, s_yw, s_yo, a0, a1, a2);
    do_cfg< 5776,  16618, 2, 2>( 4, bk, ox, s_yw, s_yo, a0, a1, a2);
    do_cfg< 5766,  22394, 2, 2>( 5, bk, ox, s_yw, s_yo, a0, a1, a2);
    do_cfg<14504,  28160, 2, 2>( 6, bk, ox, s_yw, s_yo, a0, a1, a2);
    do_cfg<14400,  42664, 2, 2>( 7, bk, ox, s_yw, s_yo, a0, a1, a2);
    do_cfg<14504,  57064, 2, 2>( 8, bk, ox, s_yw, s_yo, a0, a1, a2);
    do_cfg<23064,  71568, 2, 2>( 9, bk, ox, s_yw, s_yo, a0, a1, a2);
    do_cfg<23104,  94632, 2, 2>(10, bk, ox, s_yw, s_yo, a0, a1, a2);
    do_cfg<23064, 117736, 2, 2>(11, bk, ox, s_yw, s_yo, a0, a1, a2);
    do_cfg<36660, 140800, 3, 2>(12, bk, ox, s_yw, s_yo, a0, a1, a2);
    do_cfg<36864, 177460, 2, 2>(13, bk, ox, s_yw, s_yo, a0, a1, a2);
    do_cfg<36660, 214324, 2, 3>(14, bk, ox, s_yw, s_yo, a0, a1, a2);
    do_cfg<58312, 250984, 3, 2>(15, bk, ox, s_yw, s_yo, a0, a1, a2);
    do_cfg<58081, 309296, 3, 3>(16, bk, ox, s_yw, s_yo, a0, a1, a2);
    do_cfg<58312, 367377, 2, 3>(17, bk, ox, s_yw, s_yo, a0, a1, a2);
    do_cfg<92504, 425689, 4, 3>(18, bk, ox, s_yw, s_yo, a0, a1, a2);
    do_cfg<92416, 518193, 3, 3>(19, bk, ox, s_yw, s_yo, a0, a1, a2);
    do_cfg<92504, 610609, 3, 4>(20, bk, ox, s_yw, s_yo, a0, a1, a2);

    float* o = out + ((size_t)(bk * 224 + oy) * 224 + ox) * 3;
    o[0] = a0;
    o[1] = a1;
    o[2] = a2;
}

// ---------------------------------------------------------------------------
extern "C" void kernel_launch(void* const* d_in, const int* in_sizes, int n_in,
                              void* d_out, int out_size) {
    const float* x  = (const float*)d_in[0];
    const float* w3 = (const float*)d_in[1];
    const float* w4 = (const float*)d_in[2];
    const float* w5 = (const float*)d_in[3];

    prep_kernel<<<TOTROWS + 42, 448>>>(x);

    // p3: max area 5776 -> 23 blocks; p4: 23104 -> 91 blocks
    agg34_kernel<32, 14, 6, 0><<<dim3(23, 8, 6), 256>>>(w3);
    agg34_kernel<64, 7, 6, 6><<<dim3(91, 8, 6), 256>>>(w4);
    agg5_kernel<<<dim3(2, 8 * 373, 9), 256>>>(w5);

    dim3 gridB(224, 32);
    resize_kernel<<<gridB, 224>>>((float*)d_out);
}

// round 15
// speedup vs baseline: 1.8533x; 1.0794x over previous
#include <cuda_runtime.h>
#include <cuda_fp16.h>

#define NCFG 21

__constant__ int c_kh[NCFG] = {74,60,49,93,76,62, 148,120,98,186,152,124,
                               235,192,156,296,241,197,373,304,248};
__constant__ int c_kw[NCFG] = {49,60,74,62,76,93, 98,120,148,124,152,186,
                               156,192,235,197,241,296,248,304,373};
__constant__ int c_off[NCFG] = {0,3626,7226,10852,16618,22394,
                                28160,42664,57064,71568,94632,117736,
                                140800,177460,214324,250984,309296,367377,
                                425689,518193,610609};
// total area = 703113 pixels; scratch: [cfg][bk(32)][pixel], half4 packed in float2
#define TOTAL_AGG 22499616
__device__ float2 g_aggh[TOTAL_AGG];   // 180 MB

// x pitched with column AND per-batch row guards.
#define PITCH  768
#define XOFF   128
#define ROWOFF 64
#define RPB    576
#define TOTROWS (8 * RPB)      // 4608
__device__ float4 g_xp[TOTROWS * PITCH];   // 56.6 MB

// Tap tables
__device__ float4 g_tyw[NCFG][224];
__device__ int4   g_tyo[NCFG][224];   // row offsets premultiplied by kw
__device__ float4 g_txw[NCFG][224];
__device__ int4   g_txo[NCFG][224];   // column offsets (float2 units)

// ---------------- packed f32x2 helpers ----------------
__device__ __forceinline__ unsigned long long f2pack(float lo, float hi) {
    unsigned long long r;
    asm("mov.b64 %0, {%1, %2};" : "=l"(r) : "f"(lo), "f"(hi));
    return r;
}
__device__ __forceinline__ void funpack(unsigned long long v, float& lo, float& hi) {
    asm("mov.b64 {%0, %1}, %2;" : "=f"(lo), "=f"(hi) : "l"(v));
}
__device__ __forceinline__ void ffma2(unsigned long long& d,
                                      unsigned long long a, unsigned long long b) {
    asm("fma.rn.f32x2 %0, %1, %2, %0;" : "+l"(d) : "l"(a), "l"(b));
}

__device__ __forceinline__ float2 pack_h4(float a, float b, float c) {
    union { float2 f; __half2 h[2]; } u;
    u.h[0] = __floats2half2_rn(a, b);
    u.h[1] = __floats2half2_rn(c, 0.0f);
    return u.f;
}

// ---------------------------------------------------------------------------
// Prep: blocks [0,4608) fill one pitched row each (data or zero guard row);
// blocks [4608,4650) compute taps. Block = 448 threads.
// ---------------------------------------------------------------------------
__global__ void __launch_bounds__(448) prep_kernel(const float* __restrict__ x) {
    if (blockIdx.x < TOTROWS) {
        const int rb = blockIdx.x;
        const int b    = rb / RPB;
        const int rloc = rb - b * RPB;
        const int r    = rloc - ROWOFF;
        const int t  = threadIdx.x;
        float4* drow = g_xp + (size_t)rb * PITCH;
        const float4 z = make_float4(0.f, 0.f, 0.f, 0.f);
        if ((unsigned)r < 448u) {
            if (t < 128)      drow[t] = z;                       // left strip
            else if (t < 320) drow[XOFF + 448 + (t - 128)] = z;  // right strip
            const float* src = x + ((size_t)(b * 448 + r) * 448 + t) * 3;
            drow[XOFF + t] = make_float4(src[0], src[1], src[2], 0.0f);
        } else {
            drow[t] = z;
            if (t < 320) drow[448 + t] = z;
        }
        return;
    }
    const int bi  = blockIdx.x - TOTROWS;   // 0..41
    const int cfg = bi % NCFG;
    const int dim = bi / NCFG;              // 0 = rows(kh), 1 = cols(kw)
    const int o   = threadIdx.x;
    if (o >= 224) return;

    const int n  = dim ? c_kw[cfg] : c_kh[cfg];
    const int kw = c_kw[cfg];

    const double ks = (n > 224) ? (double)n / 224.0 : 1.0;
    const double sf = ((double)o + 0.5) * (double)n / 224.0 - 0.5;
    const int NT = (n < 224) ? 2 : (2 * n) / 224 + 1;   // 2..4
    int lo = (int)ceil(sf - ks);

    double w[4];
    double tot = 0.0;
    for (int t = 0; t < 4; ++t) {
        double v = 0.0;
        if (t < NT) {
            int j = lo + t;
            if (j >= 0 && j < n) {
                v = 1.0 - fabs(sf - (double)j) / ks;
                if (v < 0.0) v = 0.0;
            }
        }
        w[t] = v;
        tot += v;
    }
    const double r = 1.0 / tot;

    float wf[4];
    int   of[4];
    for (int t = 0; t < 4; ++t) {
        wf[t] = (float)(w[t] * r);
        int j = lo + t;
        if (j < 0) j = 0;
        if (j > n - 1) j = n - 1;
        of[t] = dim ? j : j * kw;
    }
    if (dim == 0) {
        g_tyw[cfg][o] = make_float4(wf[0], wf[1], wf[2], wf[3]);
        g_tyo[cfg][o] = make_int4(of[0], of[1], of[2], of[3]);
    } else {
        g_txw[cfg][o] = make_float4(wf[0], wf[1], wf[2], wf[3]);
        g_txo[cfg][o] = make_int4(of[0], of[1], of[2], of[3]);
    }
}

// ---------------------------------------------------------------------------
// p3/p4 agg (unchanged from R13).
// ---------------------------------------------------------------------------
template<int S, int G, int A, int CFG0>
__global__ void __launch_bounds__(256) agg34_kernel(const float* __restrict__ wsrc) {
    const int cfg = CFG0 + blockIdx.z;
    const int kh = c_kh[cfg], kw = c_kw[cfg];
    const int area = kh * kw;
    if ((int)(blockIdx.x * 256) >= area) return;

    const int a = blockIdx.z;
    const int b = blockIdx.y;
    constexpr int G2 = G * G;

    __shared__ ulonglong2 swp2[G2];   // swp2[gh] = {(k0,k1),(k2,k3)}
    {
        const float* wb = wsrc + (size_t)(b * A + a) * 4 * G2;
        for (int t = threadIdx.x; t < 2 * G2; t += 256) {
            const int gh = t >> 1, kp = t & 1;
            const float v0 = wb[(2 * kp)     * G2 + gh];
            const float v1 = wb[(2 * kp + 1) * G2 + gh];
            ((unsigned long long*)swp2)[2 * gh + kp] = f2pack(v0, v1);
        }
    }
    __syncthreads();

    const int idx = blockIdx.x * 256 + threadIdx.x;
    if (idx >= area) return;

    const int i = idx / kw;
    const int j = idx - i * kw;
    const int p0 = (kh - S + 1) >> 1;
    const int p1 = (kw - S + 1) >> 1;
    const int ri = i - p0;
    const int cj = j - p1;

    unsigned long long acc[3][2] = {{0ull,0ull},{0ull,0ull},{0ull,0ull}};

    const float4* base = g_xp + ((size_t)(b * RPB) + ROWOFF + ri) * PITCH + XOFF + cj;

#pragma unroll 2
    for (int g = 0; g < G; ++g) {
        const float4* rowp = base + g * (S * PITCH);
        const ulonglong2* wg = swp2 + g * G;
#pragma unroll 7
        for (int h = 0; h < G; ++h) {
            const float4 xv = __ldg(rowp + h * S);
            const unsigned long long xx = f2pack(xv.x, xv.x);
            const unsigned long long xy = f2pack(xv.y, xv.y);
            const unsigned long long xz = f2pack(xv.z, xv.z);
            const ulonglong2 w2 = wg[h];
            ffma2(acc[0][0], w2.x, xx);
            ffma2(acc[1][0], w2.x, xy);
            ffma2(acc[2][0], w2.x, xz);
            ffma2(acc[0][1], w2.y, xx);
            ffma2(acc[1][1], w2.y, xy);
            ffma2(acc[2][1], w2.y, xz);
        }
    }

    float2* dst = g_aggh + (size_t)32 * c_off[cfg] + (size_t)(b * 4) * area + idx;
#pragma unroll
    for (int kp = 0; kp < 2; ++kp) {
        float c0a, c0b, c1a, c1b, c2a, c2b;
        funpack(acc[0][kp], c0a, c0b);
        funpack(acc[1][kp], c1a, c1b);
        funpack(acc[2][kp], c2a, c2b);
        __stcs(dst + (size_t)(2 * kp)     * area, pack_h4(c0a, c1a, c2a));
        __stcs(dst + (size_t)(2 * kp + 1) * area, pack_h4(c0b, c1b, c2b));
    }
}

// ---------------------------------------------------------------------------
// Specialized p5 agg (unchanged from R13).
// ---------------------------------------------------------------------------
__global__ void __launch_bounds__(256) agg5_kernel(const float* __restrict__ w5) {
    const int cfg = 12 + blockIdx.z;
    const int kh = c_kh[cfg], kw = c_kw[cfg];
    const int by = blockIdx.y;
    const int b  = by / 373;
    const int i  = by - b * 373;
    if (i >= kh) return;
    const int j0 = blockIdx.x * 256;
    if (j0 >= kw) return;

    __shared__ ulonglong2 swp2[16];
    {
        const int t = threadIdx.x;
        if (t < 32) {
            const int gh = t >> 1, kp = t & 1;
            const size_t wb = (size_t)(b * 9 + blockIdx.z) * 4;
            const float v0 = w5[(wb + 2 * kp)     * 16 + gh];
            const float v1 = w5[(wb + 2 * kp + 1) * 16 + gh];
            ((unsigned long long*)swp2)[2 * gh + kp] = f2pack(v0, v1);
        }
    }
    __syncthreads();

    const int j = j0 + threadIdx.x;
    if (j >= kw) return;

    const int p0 = (kh - 127) >> 1;
    const int p1 = (kw - 127) >> 1;
    const int ri = i - p0;
    const int cj = j - p1;

    unsigned long long acc[3][2] = {{0ull,0ull},{0ull,0ull},{0ull,0ull}};

    const float4* base = g_xp + ((size_t)(b * RPB) + ROWOFF + ri) * PITCH + XOFF + cj;

#pragma unroll
    for (int g = 0; g < 4; ++g) {
        const int r = g * 128 + ri;
        if ((unsigned)r <= 447u) {
            float4 xv[4];
#pragma unroll
            for (int h = 0; h < 4; ++h)
                xv[h] = __ldg(base + g * (128 * PITCH) + h * 128);
#pragma unroll
            for (int h = 0; h < 4; ++h) {
                const unsigned long long xx = f2pack(xv[h].x, xv[h].x);
                const unsigned long long xy = f2pack(xv[h].y, xv[h].y);
                const unsigned long long xz = f2pack(xv[h].z, xv[h].z);
                const ulonglong2 w2 = swp2[g * 4 + h];
                ffma2(acc[0][0], w2.x, xx);
                ffma2(acc[1][0], w2.x, xy);
                ffma2(acc[2][0], w2.x, xz);
                ffma2(acc[0][1], w2.y, xx);
                ffma2(acc[1][1], w2.y, xy);
                ffma2(acc[2][1], w2.y, xz);
            }
        }
    }

    const int area = kh * kw;
    float2* dst = g_aggh + (size_t)32 * c_off[cfg] + (size_t)(b * 4) * area
                + (size_t)i * kw + j;
#pragma unroll
    for (int kp = 0; kp < 2; ++kp) {
        float c0a, c0b, c1a, c1b, c2a, c2b;
        funpack(acc[0][kp], c0a, c0b);
        funpack(acc[1][kp], c1a, c1b);
        funpack(acc[2][kp], c2a, c2b);
        __stcs(dst + (size_t)(2 * kp)     * area, pack_h4(c0a, c1a, c2a));
        __stcs(dst + (size_t)(2 * kp + 1) * area, pack_h4(c0b, c1b, c2b));
    }
}

// ---------------------------------------------------------------------------
// Kernel B: resize, 2 bk slices per thread (bk, bk+16). Tap math shared,
// loads doubled and independent -> 2x MLP, half the warps.
// ---------------------------------------------------------------------------
template<int AREA, int OFF, int NR, int NC>
__device__ __forceinline__ void do_cfg2(int cfg, int bk, int ox,
                                        const float (*s_yw)[4], const int (*s_yo)[4],
                                        float* A0, float* A1) {
    const float2* base0 = g_aggh + (size_t)32 * OFF + (size_t)bk * AREA;
    const float2* base1 = base0 + (size_t)16 * AREA;
    const float4 xw = g_txw[cfg][ox];
    const int4   xo = g_txo[cfg][ox];
    const float xwv[4] = {xw.x, xw.y, xw.z, xw.w};
    const int   xov[4] = {xo.x, xo.y, xo.z, xo.w};
#pragma unroll
    for (int r = 0; r < NR; ++r) {
        const float wy = s_yw[cfg][r];
        const int ro = s_yo[cfg][r];
#pragma unroll
        for (int c = 0; c < NC; ++c) {
            const float w = wy * xwv[c];
            const size_t off = (size_t)ro + xov[c];
            union { float2 f; __half2 h[2]; } u0, u1;
            u0.f = __ldg(base0 + off);
            u1.f = __ldg(base1 + off);
            const float2 l0 = __half22float2(u0.h[0]);
            const float  h0 = __low2float(u0.h[1]);
            const float2 l1 = __half22float2(u1.h[0]);
            const float  h1 = __low2float(u1.h[1]);
            A0[0] += w * l0.x;  A0[1] += w * l0.y;  A0[2] += w * h0;
            A1[0] += w * l1.x;  A1[1] += w * l1.y;  A1[2] += w * h1;
        }
    }
}

__global__ void __launch_bounds__(224) resize_kernel(float* __restrict__ out) {
    const int oy = blockIdx.x;
    const int bk = blockIdx.y;          // 0..15; pair (bk, bk+16)
    const int ox = threadIdx.x;

    __shared__ float s_yw[NCFG][4];
    __shared__ int   s_yo[NCFG][4];
    {
        const int t = threadIdx.x;
        if (t < NCFG * 4) {
            const int cfg = t >> 2, k = t & 3;
            s_yw[cfg][k] = ((const float*)&g_tyw[cfg][oy])[k];
            s_yo[cfg][k] = ((const int*)&g_tyo[cfg][oy])[k];
        }
    }
    __syncthreads();

    float A0[3] = {0.f, 0.f, 0.f};
    float A1[3] = {0.f, 0.f, 0.f};

    do_cfg2< 3626,      0, 2, 2>( 0, bk, ox, s_yw, s_yo, A0, A1);
    do_cfg2< 3600,   3626, 2, 2>( 1, bk, ox, s_yw, s_yo, A0, A1);
    do_cfg2< 3626,   7226, 2, 2>( 2, bk, ox, s_yw, s_yo, A0, A1);
    do_cfg2< 5766,  10852, 2, 2>( 3, bk, ox, s_yw, s_yo, A0, A1);
    do_cfg2< 5776,  16618, 2, 2>( 4, bk, ox, s_yw, s_yo, A0, A1);
    do_cfg2< 5766,  22394, 2, 2>( 5, bk, ox, s_yw, s_yo, A0, A1);
    do_cfg2<14504,  28160, 2, 2>( 6, bk, ox, s_yw, s_yo, A0, A1);
    do_cfg2<14400,  42664, 2, 2>( 7, bk, ox, s_yw, s_yo, A0, A1);
    do_cfg2<14504,  57064, 2, 2>( 8, bk, ox, s_yw, s_yo, A0, A1);
    do_cfg2<23064,  71568, 2, 2>( 9, bk, ox, s_yw, s_yo, A0, A1);
    do_cfg2<23104,  94632, 2, 2>(10, bk, ox, s_yw, s_yo, A0, A1);
    do_cfg2<23064, 117736, 2, 2>(11, bk, ox, s_yw, s_yo, A0, A1);
    do_cfg2<36660, 140800, 3, 2>(12, bk, ox, s_yw, s_yo, A0, A1);
    do_cfg2<36864, 177460, 2, 2>(13, bk, ox, s_yw, s_yo, A0, A1);
    do_cfg2<36660, 214324, 2, 3>(14, bk, ox, s_yw, s_yo, A0, A1);
    do_cfg2<58312, 250984, 3, 2>(15, bk, ox, s_yw, s_yo, A0, A1);
    do_cfg2<58081, 309296, 3, 3>(16, bk, ox, s_yw, s_yo, A0, A1);
    do_cfg2<58312, 367377, 2, 3>(17, bk, ox, s_yw, s_yo, A0, A1);
    do_cfg2<92504, 425689, 4, 3>(18, bk, ox, s_yw, s_yo, A0, A1);
    do_cfg2<92416, 518193, 3, 3>(19, bk, ox, s_yw, s_yo, A0, A1);
    do_cfg2<92504, 610609, 3, 4>(20, bk, ox, s_yw, s_yo, A0, A1);

    float* o0 = out + ((size_t)(bk * 224 + oy) * 224 + ox) * 3;
    o0[0] = A0[0];  o0[1] = A0[1];  o0[2] = A0[2];
    float* o1 = out + ((size_t)((bk + 16) * 224 + oy) * 224 + ox) * 3;
    o1[0] = A1[0];  o1[1] = A1[1];  o1[2] = A1[2];
}

// ---------------------------------------------------------------------------
extern "C" void kernel_launch(void* const* d_in, const int* in_sizes, int n_in,
                              void* d_out, int out_size) {
    const float* x  = (const float*)d_in[0];
    const float* w3 = (const float*)d_in[1];
    const float* w4 = (const float*)d_in[2];
    const float* w5 = (const float*)d_in[3];

    prep_kernel<<<TOTROWS + 42, 448>>>(x);

    agg34_kernel<32, 14, 6, 0><<<dim3(23, 8, 6), 256>>>(w3);
    agg34_kernel<64, 7, 6, 6><<<dim3(91, 8, 6), 256>>>(w4);
    agg5_kernel<<<dim3(2, 8 * 373, 9), 256>>>(w5);

    dim3 gridB(224, 16);   // 2 bk slices per thread
    resize_kernel<<<gridB, 224>>>((float*)d_out);
}

// round 16
// speedup vs baseline: 1.9103x; 1.0307x over previous
#include <cuda_runtime.h>
#include <cuda_fp16.h>

#define NCFG 21

__constant__ int c_kh[NCFG] = {74,60,49,93,76,62, 148,120,98,186,152,124,
                               235,192,156,296,241,197,373,304,248};
__constant__ int c_kw[NCFG] = {49,60,74,62,76,93, 98,120,148,124,152,186,
                               156,192,235,197,241,296,248,304,373};
__constant__ int c_off[NCFG] = {0,3626,7226,10852,16618,22394,
                                28160,42664,57064,71568,94632,117736,
                                140800,177460,214324,250984,309296,367377,
                                425689,518193,610609};
// total area = 703113 pixels; scratch: [cfg][bk(32)][pixel], half4 packed in float2
#define TOTAL_AGG 22499616
__device__ float2 g_aggh[TOTAL_AGG];   // 180 MB

// x pitched with column AND per-batch row guards.
#define PITCH  768
#define XOFF   128
#define ROWOFF 64
#define RPB    576
#define TOTROWS (8 * RPB)      // 4608
__device__ float4 g_xp[TOTROWS * PITCH];   // 56.6 MB

// Tap tables
__device__ float4 g_tyw[NCFG][224];
__device__ int4   g_tyo[NCFG][224];   // row offsets premultiplied by kw
__device__ float4 g_txw[NCFG][224];
__device__ int4   g_txo[NCFG][224];   // column offsets (float2 units)

// ---------------- packed f32x2 helpers ----------------
__device__ __forceinline__ unsigned long long f2pack(float lo, float hi) {
    unsigned long long r;
    asm("mov.b64 %0, {%1, %2};" : "=l"(r) : "f"(lo), "f"(hi));
    return r;
}
__device__ __forceinline__ void funpack(unsigned long long v, float& lo, float& hi) {
    asm("mov.b64 {%0, %1}, %2;" : "=f"(lo), "=f"(hi) : "l"(v));
}
__device__ __forceinline__ void ffma2(unsigned long long& d,
                                      unsigned long long a, unsigned long long b) {
    asm("fma.rn.f32x2 %0, %1, %2, %0;" : "+l"(d) : "l"(a), "l"(b));
}

__device__ __forceinline__ float2 pack_h4(float a, float b, float c) {
    union { float2 f; __half2 h[2]; } u;
    u.h[0] = __floats2half2_rn(a, b);
    u.h[1] = __floats2half2_rn(c, 0.0f);
    return u.f;
}

// ---------------------------------------------------------------------------
// Prep: blocks [0,4608) fill one pitched row each (data or zero guard row);
// blocks [4608,4650) compute taps. Block = 448 threads.
// ---------------------------------------------------------------------------
__global__ void __launch_bounds__(448) prep_kernel(const float* __restrict__ x) {
    if (blockIdx.x < TOTROWS) {
        const int rb = blockIdx.x;
        const int b    = rb / RPB;
        const int rloc = rb - b * RPB;
        const int r    = rloc - ROWOFF;
        const int t  = threadIdx.x;
        float4* drow = g_xp + (size_t)rb * PITCH;
        const float4 z = make_float4(0.f, 0.f, 0.f, 0.f);
        if ((unsigned)r < 448u) {
            if (t < 128)      drow[t] = z;                       // left strip
            else if (t < 320) drow[XOFF + 448 + (t - 128)] = z;  // right strip
            const float* src = x + ((size_t)(b * 448 + r) * 448 + t) * 3;
            drow[XOFF + t] = make_float4(src[0], src[1], src[2], 0.0f);
        } else {
            drow[t] = z;
            if (t < 320) drow[448 + t] = z;
        }
        return;
    }
    const int bi  = blockIdx.x - TOTROWS;   // 0..41
    const int cfg = bi % NCFG;
    const int dim = bi / NCFG;              // 0 = rows(kh), 1 = cols(kw)
    const int o   = threadIdx.x;
    if (o >= 224) return;

    const int n  = dim ? c_kw[cfg] : c_kh[cfg];
    const int kw = c_kw[cfg];

    const double ks = (n > 224) ? (double)n / 224.0 : 1.0;
    const double sf = ((double)o + 0.5) * (double)n / 224.0 - 0.5;
    const int NT = (n < 224) ? 2 : (2 * n) / 224 + 1;   // 2..4
    int lo = (int)ceil(sf - ks);

    double w[4];
    double tot = 0.0;
    for (int t = 0; t < 4; ++t) {
        double v = 0.0;
        if (t < NT) {
            int j = lo + t;
            if (j >= 0 && j < n) {
                v = 1.0 - fabs(sf - (double)j) / ks;
                if (v < 0.0) v = 0.0;
            }
        }
        w[t] = v;
        tot += v;
    }
    const double r = 1.0 / tot;

    float wf[4];
    int   of[4];
    for (int t = 0; t < 4; ++t) {
        wf[t] = (float)(w[t] * r);
        int j = lo + t;
        if (j < 0) j = 0;
        if (j > n - 1) j = n - 1;
        of[t] = dim ? j : j * kw;
    }
    if (dim == 0) {
        g_tyw[cfg][o] = make_float4(wf[0], wf[1], wf[2], wf[3]);
        g_tyo[cfg][o] = make_int4(of[0], of[1], of[2], of[3]);
    } else {
        g_txw[cfg][o] = make_float4(wf[0], wf[1], wf[2], wf[3]);
        g_txo[cfg][o] = make_int4(of[0], of[1], of[2], of[3]);
    }
}

// ---------------------------------------------------------------------------
// p3/p4 agg (unchanged from R13).
// ---------------------------------------------------------------------------
template<int S, int G, int A, int CFG0>
__global__ void __launch_bounds__(256) agg34_kernel(const float* __restrict__ wsrc) {
    const int cfg = CFG0 + blockIdx.z;
    const int kh = c_kh[cfg], kw = c_kw[cfg];
    const int area = kh * kw;
    if ((int)(blockIdx.x * 256) >= area) return;

    const int a = blockIdx.z;
    const int b = blockIdx.y;
    constexpr int G2 = G * G;

    __shared__ ulonglong2 swp2[G2];   // swp2[gh] = {(k0,k1),(k2,k3)}
    {
        const float* wb = wsrc + (size_t)(b * A + a) * 4 * G2;
        for (int t = threadIdx.x; t < 2 * G2; t += 256) {
            const int gh = t >> 1, kp = t & 1;
            const float v0 = wb[(2 * kp)     * G2 + gh];
            const float v1 = wb[(2 * kp + 1) * G2 + gh];
            ((unsigned long long*)swp2)[2 * gh + kp] = f2pack(v0, v1);
        }
    }
    __syncthreads();

    const int idx = blockIdx.x * 256 + threadIdx.x;
    if (idx >= area) return;

    const int i = idx / kw;
    const int j = idx - i * kw;
    const int p0 = (kh - S + 1) >> 1;
    const int p1 = (kw - S + 1) >> 1;
    const int ri = i - p0;
    const int cj = j - p1;

    unsigned long long acc[3][2] = {{0ull,0ull},{0ull,0ull},{0ull,0ull}};

    const float4* base = g_xp + ((size_t)(b * RPB) + ROWOFF + ri) * PITCH + XOFF + cj;

#pragma unroll 2
    for (int g = 0; g < G; ++g) {
        const float4* rowp = base + g * (S * PITCH);
        const ulonglong2* wg = swp2 + g * G;
#pragma unroll 7
        for (int h = 0; h < G; ++h) {
            const float4 xv = __ldg(rowp + h * S);
            const unsigned long long xx = f2pack(xv.x, xv.x);
            const unsigned long long xy = f2pack(xv.y, xv.y);
            const unsigned long long xz = f2pack(xv.z, xv.z);
            const ulonglong2 w2 = wg[h];
            ffma2(acc[0][0], w2.x, xx);
            ffma2(acc[1][0], w2.x, xy);
            ffma2(acc[2][0], w2.x, xz);
            ffma2(acc[0][1], w2.y, xx);
            ffma2(acc[1][1], w2.y, xy);
            ffma2(acc[2][1], w2.y, xz);
        }
    }

    float2* dst = g_aggh + (size_t)32 * c_off[cfg] + (size_t)(b * 4) * area + idx;
#pragma unroll
    for (int kp = 0; kp < 2; ++kp) {
        float c0a, c0b, c1a, c1b, c2a, c2b;
        funpack(acc[0][kp], c0a, c0b);
        funpack(acc[1][kp], c1a, c1b);
        funpack(acc[2][kp], c2a, c2b);
        __stcs(dst + (size_t)(2 * kp)     * area, pack_h4(c0a, c1a, c2a));
        __stcs(dst + (size_t)(2 * kp + 1) * area, pack_h4(c0b, c1b, c2b));
    }
}

// ---------------------------------------------------------------------------
// Specialized p5 agg (unchanged from R13).
// ---------------------------------------------------------------------------
__global__ void __launch_bounds__(256) agg5_kernel(const float* __restrict__ w5) {
    const int cfg = 12 + blockIdx.z;
    const int kh = c_kh[cfg], kw = c_kw[cfg];
    const int by = blockIdx.y;
    const int b  = by / 373;
    const int i  = by - b * 373;
    if (i >= kh) return;
    const int j0 = blockIdx.x * 256;
    if (j0 >= kw) return;

    __shared__ ulonglong2 swp2[16];
    {
        const int t = threadIdx.x;
        if (t < 32) {
            const int gh = t >> 1, kp = t & 1;
            const size_t wb = (size_t)(b * 9 + blockIdx.z) * 4;
            const float v0 = w5[(wb + 2 * kp)     * 16 + gh];
            const float v1 = w5[(wb + 2 * kp + 1) * 16 + gh];
            ((unsigned long long*)swp2)[2 * gh + kp] = f2pack(v0, v1);
        }
    }
    __syncthreads();

    const int j = j0 + threadIdx.x;
    if (j >= kw) return;

    const int p0 = (kh - 127) >> 1;
    const int p1 = (kw - 127) >> 1;
    const int ri = i - p0;
    const int cj = j - p1;

    unsigned long long acc[3][2] = {{0ull,0ull},{0ull,0ull},{0ull,0ull}};

    const float4* base = g_xp + ((size_t)(b * RPB) + ROWOFF + ri) * PITCH + XOFF + cj;

#pragma unroll
    for (int g = 0; g < 4; ++g) {
        const int r = g * 128 + ri;
        if ((unsigned)r <= 447u) {
            float4 xv[4];
#pragma unroll
            for (int h = 0; h < 4; ++h)
                xv[h] = __ldg(base + g * (128 * PITCH) + h * 128);
#pragma unroll
            for (int h = 0; h < 4; ++h) {
                const unsigned long long xx = f2pack(xv[h].x, xv[h].x);
                const unsigned long long xy = f2pack(xv[h].y, xv[h].y);
                const unsigned long long xz = f2pack(xv[h].z, xv[h].z);
                const ulonglong2 w2 = swp2[g * 4 + h];
                ffma2(acc[0][0], w2.x, xx);
                ffma2(acc[1][0], w2.x, xy);
                ffma2(acc[2][0], w2.x, xz);
                ffma2(acc[0][1], w2.y, xx);
                ffma2(acc[1][1], w2.y, xy);
                ffma2(acc[2][1], w2.y, xz);
            }
        }
    }

    const int area = kh * kw;
    float2* dst = g_aggh + (size_t)32 * c_off[cfg] + (size_t)(b * 4) * area
                + (size_t)i * kw + j;
#pragma unroll
    for (int kp = 0; kp < 2; ++kp) {
        float c0a, c0b, c1a, c1b, c2a, c2b;
        funpack(acc[0][kp], c0a, c0b);
        funpack(acc[1][kp], c1a, c1b);
        funpack(acc[2][kp], c2a, c2b);
        __stcs(dst + (size_t)(2 * kp)     * area, pack_h4(c0a, c1a, c2a));
        __stcs(dst + (size_t)(2 * kp + 1) * area, pack_h4(c0b, c1b, c2b));
    }
}

// ---------------------------------------------------------------------------
// Kernel B: resize, 4 bk slices per thread (bk, bk+8, bk+16, bk+24).
// Tap math shared, 4 independent loads per tap -> 4x MLP, quarter warps.
// ---------------------------------------------------------------------------
template<int AREA, int OFF, int NR, int NC>
__device__ __forceinline__ void do_cfg4(int cfg, int bk, int ox,
                                        const float (*s_yw)[4], const int (*s_yo)[4],
                                        float* A0, float* A1, float* A2, float* A3) {
    const float2* base0 = g_aggh + (size_t)32 * OFF + (size_t)bk * AREA;
    const float2* base1 = base0 + (size_t)8  * AREA;
    const float2* base2 = base0 + (size_t)16 * AREA;
    const float2* base3 = base0 + (size_t)24 * AREA;
    const float4 xw = g_txw[cfg][ox];
    const int4   xo = g_txo[cfg][ox];
    const float xwv[4] = {xw.x, xw.y, xw.z, xw.w};
    const int   xov[4] = {xo.x, xo.y, xo.z, xo.w};
#pragma unroll
    for (int r = 0; r < NR; ++r) {
        const float wy = s_yw[cfg][r];
        const int ro = s_yo[cfg][r];
#pragma unroll
        for (int c = 0; c < NC; ++c) {
            const float w = wy * xwv[c];
            const size_t off = (size_t)ro + xov[c];
            union { float2 f; __half2 h[2]; } u0, u1, u2, u3;
            u0.f = __ldg(base0 + off);
            u1.f = __ldg(base1 + off);
            u2.f = __ldg(base2 + off);
            u3.f = __ldg(base3 + off);
            const float2 l0 = __half22float2(u0.h[0]);
            const float  h0 = __low2float(u0.h[1]);
            const float2 l1 = __half22float2(u1.h[0]);
            const float  h1 = __low2float(u1.h[1]);
            const float2 l2 = __half22float2(u2.h[0]);
            const float  h2 = __low2float(u2.h[1]);
            const float2 l3 = __half22float2(u3.h[0]);
            const float  h3 = __low2float(u3.h[1]);
            A0[0] += w * l0.x;  A0[1] += w * l0.y;  A0[2] += w * h0;
            A1[0] += w * l1.x;  A1[1] += w * l1.y;  A1[2] += w * h1;
            A2[0] += w * l2.x;  A2[1] += w * l2.y;  A2[2] += w * h2;
            A3[0] += w * l3.x;  A3[1] += w * l3.y;  A3[2] += w * h3;
        }
    }
}

__global__ void __launch_bounds__(224) resize_kernel(float* __restrict__ out) {
    const int oy = blockIdx.x;
    const int bk = blockIdx.y;          // 0..7; slices bk, bk+8, bk+16, bk+24
    const int ox = threadIdx.x;

    __shared__ float s_yw[NCFG][4];
    __shared__ int   s_yo[NCFG][4];
    {
        const int t = threadIdx.x;
        if (t < NCFG * 4) {
            const int cfg = t >> 2, k = t & 3;
            s_yw[cfg][k] = ((const float*)&g_tyw[cfg][oy])[k];
            s_yo[cfg][k] = ((const int*)&g_tyo[cfg][oy])[k];
        }
    }
    __syncthreads();

    float A0[3] = {0.f, 0.f, 0.f};
    float A1[3] = {0.f, 0.f, 0.f};
    float A2[3] = {0.f, 0.f, 0.f};
    float A3[3] = {0.f, 0.f, 0.f};

    do_cfg4< 3626,      0, 2, 2>( 0, bk, ox, s_yw, s_yo, A0, A1, A2, A3);
    do_cfg4< 3600,   3626, 2, 2>( 1, bk, ox, s_yw, s_yo, A0, A1, A2, A3);
    do_cfg4< 3626,   7226, 2, 2>( 2, bk, ox, s_yw, s_yo, A0, A1, A2, A3);
    do_cfg4< 5766,  10852, 2, 2>( 3, bk, ox, s_yw, s_yo, A0, A1, A2, A3);
    do_cfg4< 5776,  16618, 2, 2>( 4, bk, ox, s_yw, s_yo, A0, A1, A2, A3);
    do_cfg4< 5766,  22394, 2, 2>( 5, bk, ox, s_yw, s_yo, A0, A1, A2, A3);
    do_cfg4<14504,  28160, 2, 2>( 6, bk, ox, s_yw, s_yo, A0, A1, A2, A3);
    do_cfg4<14400,  42664, 2, 2>( 7, bk, ox, s_yw, s_yo, A0, A1, A2, A3);
    do_cfg4<14504,  57064, 2, 2>( 8, bk, ox, s_yw, s_yo, A0, A1, A2, A3);
    do_cfg4<23064,  71568, 2, 2>( 9, bk, ox, s_yw, s_yo, A0, A1, A2, A3);
    do_cfg4<23104,  94632, 2, 2>(10, bk, ox, s_yw, s_yo, A0, A1, A2, A3);
    do_cfg4<23064, 117736, 2, 2>(11, bk, ox, s_yw, s_yo, A0, A1, A2, A3);
    do_cfg4<36660, 140800, 3, 2>(12, bk, ox, s_yw, s_yo, A0, A1, A2, A3);
    do_cfg4<36864, 177460, 2, 2>(13, bk, ox, s_yw, s_yo, A0, A1, A2, A3);
    do_cfg4<36660, 214324, 2, 3>(14, bk, ox, s_yw, s_yo, A0, A1, A2, A3);
    do_cfg4<58312, 250984, 3, 2>(15, bk, ox, s_yw, s_yo, A0, A1, A2, A3);
    do_cfg4<58081, 309296, 3, 3>(16, bk, ox, s_yw, s_yo, A0, A1, A2, A3);
    do_cfg4<58312, 367377, 2, 3>(17, bk, ox, s_yw, s_yo, A0, A1, A2, A3);
    do_cfg4<92504, 425689, 4, 3>(18, bk, ox, s_yw, s_yo, A0, A1, A2, A3);
    do_cfg4<92416, 518193, 3, 3>(19, bk, ox, s_yw, s_yo, A0, A1, A2, A3);
    do_cfg4<92504, 610609, 3, 4>(20, bk, ox, s_yw, s_yo, A0, A1, A2, A3);

    float* o0 = out + ((size_t)(bk * 224 + oy) * 224 + ox) * 3;
    o0[0] = A0[0];  o0[1] = A0[1];  o0[2] = A0[2];
    float* o1 = out + ((size_t)((bk + 8) * 224 + oy) * 224 + ox) * 3;
    o1[0] = A1[0];  o1[1] = A1[1];  o1[2] = A1[2];
    float* o2 = out + ((size_t)((bk + 16) * 224 + oy) * 224 + ox) * 3;
    o2[0] = A2[0];  o2[1] = A2[1];  o2[2] = A2[2];
    float* o3 = out + ((size_t)((bk + 24) * 224 + oy) * 224 + ox) * 3;
    o3[0] = A3[0];  o3[1] = A3[1];  o3[2] = A3[2];
}

// ---------------------------------------------------------------------------
extern "C" void kernel_launch(void* const* d_in, const int* in_sizes, int n_in,
                              void* d_out, int out_size) {
    const float* x  = (const float*)d_in[0];
    const float* w3 = (const float*)d_in[1];
    const float* w4 = (const float*)d_in[2];
    const float* w5 = (const float*)d_in[3];

    prep_kernel<<<TOTROWS + 42, 448>>>(x);

    agg34_kernel<32, 14, 6, 0><<<dim3(23, 8, 6), 256>>>(w3);
    agg34_kernel<64, 7, 6, 6><<<dim3(91, 8, 6), 256>>>(w4);
    agg5_kernel<<<dim3(2, 8 * 373, 9), 256>>>(w5);

    dim3 gridB(224, 8);   // 4 bk slices per thread
    resize_kernel<<<gridB, 224>>>((float*)d_out);
}